// round 16
// baseline (speedup 1.0000x reference)
#include <cuda_runtime.h>
#include <cuda_fp16.h>
#include <stdint.h>

// ---------------- problem constants ----------------
#define TSTEPS 512
#define BSZ    256
#define NIN    128
#define NHID   512
#define NOUT   10
#define DTc    0.042f
#define GAMc   2.7f
#define EPSc   4.7f

// ---------------- kernel config ----------------
#define NCTA    128          // 8 M-tiles(32) x 16 N-tiles(32)
#define KW      16           // warps; each = m32 x n32, k-slice of 64 (state part)
#define THREADS (KW*32)      // 512
#define PS      36           // partial row stride (words; float2-aligned)

// counter per (t, mi) on its own 256B line; 256 per-warp arrivals each
#define BARIDX(t, mi) ((((t) * 8) + (mi)) * 64)
#define ARRIVALS 256u

#define SMEM_BYTES (KW * 32 * PS * 4)   // 73,728 B partial buffer

// ---------------- device scratch ----------------
// fp16 state, R14-proven block-pair-interleaved layout:
//   g_H[buf][ ((mi*4+slice)*4 + m) ][ row(32) ][ 16 u32 ]
// pair p of k16-block j (j = 2m + j1) at pos(p,j1) = (p&3)*4 + (p>>2)*2 + j1.
// Consumer lane (rr, c): uint4 at row*16 + c*4 -> one LDG.128 feeds TWO mma k-steps.
__device__ unsigned g_Hz[2][8*4*4*32*16];              // 65536 u32 per buffer
__device__ unsigned g_Hy[2][8*4*4*32*16];
__device__ float    g_preX[(size_t)NCTA*TSTEPS*32*32]; // x@Wx + bias, per-CTA patches
__device__ float    g_hyf[BSZ*NHID];                   // final hy (fp32)
__device__ unsigned g_bar[(TSTEPS+1)*8*64];            // padded (t,mi) counters
__device__ unsigned g_fin[8];                          // final per-mi CTA counters

// ---------------- helpers ----------------
__device__ __forceinline__ float fast_tanh(float v) {
    float e = __expf(2.0f * v);
    return 1.0f - __fdividef(2.0f, e + 1.0f);
}
__device__ __forceinline__ unsigned pack_h2(float lo, float hi) {
    __half2 h = __floats2half2_rn(lo, hi);
    return *reinterpret_cast<unsigned*>(&h);
}
__device__ __forceinline__ void mma_f16(float* d,
                                        unsigned a0, unsigned a1, unsigned a2, unsigned a3,
                                        unsigned b0, unsigned b1) {
    asm volatile("mma.sync.aligned.m16n8k16.row.col.f32.f16.f16.f32 "
                 "{%0,%1,%2,%3}, {%4,%5,%6,%7}, {%8,%9}, {%0,%1,%2,%3};"
                 : "+f"(d[0]), "+f"(d[1]), "+f"(d[2]), "+f"(d[3])
                 : "r"(a0), "r"(a1), "r"(a2), "r"(a3), "r"(b0), "r"(b1));
}
__device__ __forceinline__ void bar_arrive(int idx) {
    asm volatile("red.release.gpu.global.add.u32 [%0], 1;" :: "l"(&g_bar[idx]) : "memory");
}
__device__ __forceinline__ void poll_n(int idx, unsigned n) {
    unsigned v;
    do {
        asm volatile("ld.acquire.gpu.global.u32 %0, [%1];" : "=r"(v) : "l"(&g_bar[idx]) : "memory");
    } while (v < n);
}
__device__ __forceinline__ float2 ldcg2(const float* p) {
    return __ldcg(reinterpret_cast<const float2*>(p));
}
__device__ __forceinline__ int pos_of(int p, int j1) {
    return (p & 3) * 4 + (p >> 2) * 2 + j1;
}

// ================= single persistent kernel =================
__global__ void __launch_bounds__(THREADS, 1)
cornn_persist(const float* __restrict__ x, const float* __restrict__ W,
              const float* __restrict__ bias,
              const float* __restrict__ Wout, const float* __restrict__ bout,
              float* __restrict__ out) {
    extern __shared__ float Part[];      // [KW][32][PS]

    const int tid  = threadIdx.x;
    const int cta  = blockIdx.x;
    const int mi   = cta >> 4;            // 0..7
    const int ni   = cta & 15;            // 0..15
    const int lane = tid & 31;
    const int warp = tid >> 5;            // 0..15
    const int rr   = lane >> 2;
    const int cc   = 2 * (lane & 3);

    // ================= phase 1: preX[t] = x_t @ W[0:128] + b (per-CTA patches) =================
    {
        unsigned xb0[8][4], xb1[8][4];
        const int n = ni * 32 + rr;
#pragma unroll
        for (int j = 0; j < 8; ++j) {
            const int k0 = j * 16 + cc;
#pragma unroll
            for (int nf = 0; nf < 4; ++nf) {
                const float* wp = W + (size_t)k0 * NHID + n + nf * 8;
                xb0[j][nf] = pack_h2(wp[0],        wp[NHID]);
                xb1[j][nf] = pack_h2(wp[8 * NHID], wp[9 * NHID]);
            }
        }
        float bc[4][2];
#pragma unroll
        for (int nf = 0; nf < 4; ++nf) {
            int col = ni * 32 + nf * 8 + cc;
            bc[nf][0] = bias[col];
            bc[nf][1] = bias[col + 1];
        }
        const int arow = mi * 32 + rr;
        for (int i = 0; i < TSTEPS / KW; ++i) {
            const int t = warp + KW * i;
            float acc0[4][4], acc1[4][4];
#pragma unroll
            for (int nf = 0; nf < 4; ++nf) {
                acc0[nf][0] = bc[nf][0]; acc0[nf][1] = bc[nf][1];
                acc0[nf][2] = bc[nf][0]; acc0[nf][3] = bc[nf][1];
                acc1[nf][0] = bc[nf][0]; acc1[nf][1] = bc[nf][1];
                acc1[nf][2] = bc[nf][0]; acc1[nf][3] = bc[nf][1];
            }
            const float* rx = x + ((size_t)t * BSZ + arow) * NIN + cc;
#pragma unroll
            for (int j = 0; j < 8; ++j) {
                float2 v0l = ldcg2(rx + j * 16),            v0h = ldcg2(rx + j * 16 + 8);
                float2 v1l = ldcg2(rx + 8 * NIN + j * 16),  v1h = ldcg2(rx + 8 * NIN + j * 16 + 8);
                float2 v2l = ldcg2(rx + 16 * NIN + j * 16), v2h = ldcg2(rx + 16 * NIN + j * 16 + 8);
                float2 v3l = ldcg2(rx + 24 * NIN + j * 16), v3h = ldcg2(rx + 24 * NIN + j * 16 + 8);
                unsigned a0l = pack_h2(v0l.x, v0l.y), a0h = pack_h2(v0h.x, v0h.y);
                unsigned a1l = pack_h2(v1l.x, v1l.y), a1h = pack_h2(v1h.x, v1h.y);
                unsigned a2l = pack_h2(v2l.x, v2l.y), a2h = pack_h2(v2h.x, v2h.y);
                unsigned a3l = pack_h2(v3l.x, v3l.y), a3h = pack_h2(v3h.x, v3h.y);
#pragma unroll
                for (int nf = 0; nf < 4; ++nf) {
                    mma_f16(acc0[nf], a0l, a1l, a0h, a1h, xb0[j][nf], xb1[j][nf]);
                    mma_f16(acc1[nf], a2l, a3l, a2h, a3h, xb0[j][nf], xb1[j][nf]);
                }
            }
            float* dst = g_preX + ((size_t)(cta * TSTEPS + t) * 32) * 32;
#pragma unroll
            for (int nf = 0; nf < 4; ++nf) {
                int co = nf * 8 + cc;
                __stcg((float2*)(dst + rr * 32 + co),        make_float2(acc0[nf][0], acc0[nf][1]));
                __stcg((float2*)(dst + (rr + 8) * 32 + co),  make_float2(acc0[nf][2], acc0[nf][3]));
                __stcg((float2*)(dst + (rr + 16) * 32 + co), make_float2(acc1[nf][0], acc1[nf][1]));
                __stcg((float2*)(dst + (rr + 24) * 32 + co), make_float2(acc1[nf][2], acc1[nf][3]));
            }
        }
    }

    // ================= producer store addresses (1 col-pair per thread) =================
    const int srow = tid >> 4;                 // 0..31
    const int scol = (tid & 15) * 2;           // 0,2,..,30
    const int grow = mi * 32 + srow;
    const int gcol = ni * 32 + scol;
    const int sl   = gcol >> 7;                // slice 0..3
    const int lc   = gcol & 127;
    const int jj   = lc >> 4;                  // k16-block within slice
    const int m0   = jj >> 1;                  // block-pair
    const int j1   = jj & 1;
    const int p0   = (lc & 15) >> 1;           // pair index 0..7
    const int a0i  = (((mi * 4 + sl) * 4 + m0) * 32 + srow) * 16 + pos_of(p0, j1);

    // zero initial state (buffer 0), per-warp arrive (t=0)
    __stcg(&g_Hz[0][a0i], 0u);
    __stcg(&g_Hy[0][a0i], 0u);
    __syncwarp();
    if (lane == 0) bar_arrive(BARIDX(0, mi));

    // ---- main-loop B fragments: W rows 128 + warp*64 .. +64 ----
    unsigned wb0[4][4], wb1[4][4];
    {
        const int n = ni * 32 + rr;
#pragma unroll
        for (int j = 0; j < 4; ++j) {
            const int k0 = 128 + warp * 64 + j * 16 + cc;
#pragma unroll
            for (int nf = 0; nf < 4; ++nf) {
                const float* wp = W + (size_t)k0 * NHID + n + nf * 8;
                wb0[j][nf] = pack_h2(wp[0],        wp[NHID]);
                wb1[j][nf] = pack_h2(wp[8 * NHID], wp[9 * NHID]);
            }
        }
    }

    // consumer A-fragment base: warps 0-7 -> hz cols 64w; 8-15 -> hy cols 64(w-8)
    const int wsl  = (warp & 7) >> 1;          // slice within state
    const int hoff = (mi * 4 + wsl) * 2048 + (warp & 1) * 1024 + rr * 16 + (lane & 3) * 4;

    float hyr[2] = {0, 0}, hzr[2] = {0, 0};

    // preX prefetch one step ahead (this thread's float2 patch)
    const float* pxbase = g_preX + ((size_t)cta * TSTEPS * 32 + srow) * 32 + scol;
    float2 px = ldcg2(pxbase);

    // ================= recurrence =================
    for (int t = 0; t < TSTEPS; ++t) {
        const int rb = t & 1, wbuf = rb ^ 1;

        // prefetch next step's preX patch
        const int tn = (t + 1 < TSTEPS) ? t + 1 : t;
        float2 px_next = ldcg2(pxbase + (size_t)tn * 32 * 32);

        // per-warp poll: all 256 producer-warps of this mi group published step t
        if (lane == 0) poll_n(BARIDX(t, mi), ARRIVALS);
        __syncwarp();

        const unsigned* hp = ((warp < 8) ? g_Hz[rb] : g_Hy[rb]) + hoff;

        float acc0[4][4], acc1[4][4];
#pragma unroll
        for (int nf = 0; nf < 4; ++nf)
#pragma unroll
            for (int c = 0; c < 4; ++c) { acc0[nf][c] = 0.f; acc1[nf][c] = 0.f; }

#pragma unroll
        for (int m = 0; m < 2; ++m) {
            const unsigned* q = hp + m * 512;     // local block-pair; rows +8 -> +128 u32
            uint4 u0 = __ldcg((const uint4*)(q));            // rows 0-7
            uint4 u1 = __ldcg((const uint4*)(q + 128));      // rows 8-15
            uint4 u2 = __ldcg((const uint4*)(q + 256));      // rows 16-23
            uint4 u3 = __ldcg((const uint4*)(q + 384));      // rows 24-31
            // even block (j = 2m): .x (pair c), .z (pair c+4)
#pragma unroll
            for (int nf = 0; nf < 4; ++nf) {
                mma_f16(acc0[nf], u0.x, u1.x, u0.z, u1.z, wb0[2*m][nf], wb1[2*m][nf]);
                mma_f16(acc1[nf], u2.x, u3.x, u2.z, u3.z, wb0[2*m][nf], wb1[2*m][nf]);
            }
            // odd block (j = 2m+1): .y, .w
#pragma unroll
            for (int nf = 0; nf < 4; ++nf) {
                mma_f16(acc0[nf], u0.y, u1.y, u0.w, u1.w, wb0[2*m+1][nf], wb1[2*m+1][nf]);
                mma_f16(acc1[nf], u2.y, u3.y, u2.w, u3.w, wb0[2*m+1][nf], wb1[2*m+1][nf]);
            }
        }

        // write this warp's full m32 x n32 partial
        {
            float* P = Part + warp * (32 * PS);
#pragma unroll
            for (int nf = 0; nf < 4; ++nf) {
                int co = nf * 8 + cc;
                *(float2*)(P + rr * PS + co)        = make_float2(acc0[nf][0], acc0[nf][1]);
                *(float2*)(P + (rr + 8) * PS + co)  = make_float2(acc0[nf][2], acc0[nf][3]);
                *(float2*)(P + (rr + 16) * PS + co) = make_float2(acc1[nf][0], acc1[nf][1]);
                *(float2*)(P + (rr + 24) * PS + co) = make_float2(acc1[nf][2], acc1[nf][3]);
            }
        }
        __syncthreads();   // single CTA-wide barrier: partials visible

        // reduce 16 partials + preX, tanh, state update, publish, per-warp arrive
        {
            float s0 = px.x, s1 = px.y;
#pragma unroll
            for (int p = 0; p < KW; ++p) {
                float2 v = *(const float2*)(Part + p * (32 * PS) + srow * PS + scol);
                s0 += v.x; s1 += v.y;
            }
            float pre0 = fast_tanh(s0);
            float pre1 = fast_tanh(s1);
            hzr[0] += DTc * (pre0 - GAMc * hyr[0] - EPSc * hzr[0]);  hyr[0] += DTc * hzr[0];
            hzr[1] += DTc * (pre1 - GAMc * hyr[1] - EPSc * hzr[1]);  hyr[1] += DTc * hzr[1];

            __stcg(&g_Hz[wbuf][a0i], pack_h2(hzr[0], hzr[1]));
            __stcg(&g_Hy[wbuf][a0i], pack_h2(hyr[0], hyr[1]));
            if (t == TSTEPS - 1) {
                __stcg((float2*)&g_hyf[(size_t)grow * NHID + gcol],
                       make_float2(hyr[0], hyr[1]));
            }
        }
        __syncwarp();
        if (lane == 0) bar_arrive(BARIDX(t + 1, mi));   // this warp's rows published
        px = px_next;
    }

    // ---- final wait: all 256 producer-warps of rows mi done ----
    if (tid == 0) poll_n(BARIDX(TSTEPS, mi), ARRIVALS);
    __syncthreads();

    // ---- fused output GEMM: out = hy_final @ Wout + bout ----
    if (warp < 2) {
        int row = cta * 2 + warp;
        const float* h = g_hyf + (size_t)row * NHID;
        float acc[NOUT];
#pragma unroll
        for (int o = 0; o < NOUT; ++o) acc[o] = 0.f;
        for (int k = lane; k < NHID; k += 32) {
            float hv = __ldcg(h + k);
#pragma unroll
            for (int o = 0; o < NOUT; ++o) acc[o] += hv * Wout[k * NOUT + o];
        }
#pragma unroll
        for (int o = 0; o < NOUT; ++o) {
#pragma unroll
            for (int s = 16; s > 0; s >>= 1)
                acc[o] += __shfl_xor_sync(0xffffffffu, acc[o], s);
        }
        if (lane == 0) {
#pragma unroll
            for (int o = 0; o < NOUT; ++o) out[row * NOUT + o] = acc[o] + bout[o];
        }
    }

    // ---- safe self-reset: last CTA of mi group (all pollers of mi already done) ----
    __shared__ unsigned s_last;
    if (tid == 0) {
        unsigned old = atomicAdd(&g_fin[mi], 1u);
        s_last = (old == 15u) ? 1u : 0u;
    }
    __syncthreads();
    if (s_last) {
        for (int tt = tid; tt <= TSTEPS; tt += THREADS)
            g_bar[BARIDX(tt, mi)] = 0u;
        __syncthreads();
        if (tid == 0) {
            __threadfence();
            g_fin[mi] = 0u;
        }
    }
}

// ---------------- launch ----------------
extern "C" void kernel_launch(void* const* d_in, const int* in_sizes, int n_in,
                              void* d_out, int out_size) {
    (void)in_sizes; (void)n_in; (void)out_size;
    const float* x    = (const float*)d_in[0];
    const float* W    = (const float*)d_in[1];
    const float* b    = (const float*)d_in[2];
    const float* Wout = (const float*)d_in[3];
    const float* bout = (const float*)d_in[4];
    float* out = (float*)d_out;

    cudaFuncSetAttribute(cornn_persist, cudaFuncAttributeMaxDynamicSharedMemorySize, SMEM_BYTES);
    cornn_persist<<<NCTA, THREADS, SMEM_BYTES>>>(x, W, b, Wout, bout, out);
}

// round 17
// speedup vs baseline: 1.0219x; 1.0219x over previous
#include <cuda_runtime.h>
#include <cuda_fp16.h>
#include <stdint.h>

// ---------------- problem constants ----------------
#define TSTEPS 512
#define BSZ    256
#define NIN    128
#define NHID   512
#define NOUT   10
#define DTc    0.042f
#define GAMc   2.7f
#define EPSc   4.7f

// ---------------- kernel config ----------------
#define NCTA    128          // 8 M-tiles(32) x 16 N-tiles(32)
#define KW      16           // warps = (kh 0..7) x (mh 0..1): m16 x n32 x k128
#define THREADS (KW*32)      // 512
#define PS      40           // partial row stride (words)

// counter per (t, mi) on its own 256B line; 256 per-warp arrivals each
#define BARIDX(t, mi) ((((t) * 8) + (mi)) * 64)
#define ARRIVALS 256u

// ---------------- device scratch ----------------
// fp16 state, R14-proven block-pair-interleaved layout:
//   g_H[buf][ ((mi*4+slice)*4 + m) ][ row(32) ][ 16 u32 ]
// pair p of k16-block j (j = 2m + j1) at pos(p,j1) = (p&3)*4 + (p>>2)*2 + j1.
__device__ unsigned g_Hz[2][8*4*4*32*16];              // 65536 u32 per buffer
__device__ unsigned g_Hy[2][8*4*4*32*16];
__device__ float    g_preX[(size_t)NCTA*TSTEPS*32*32]; // x@Wx + bias, per-CTA patches
__device__ float    g_hyf[BSZ*NHID];                   // final hy (fp32)
__device__ unsigned g_bar[(TSTEPS+1)*8*64];            // padded (t,mi) counters
__device__ unsigned g_fin[8];                          // final per-mi CTA counters

// ---------------- helpers ----------------
__device__ __forceinline__ float fast_tanh(float v) {
    float e = __expf(2.0f * v);
    return 1.0f - __fdividef(2.0f, e + 1.0f);
}
__device__ __forceinline__ unsigned pack_h2(float lo, float hi) {
    __half2 h = __floats2half2_rn(lo, hi);
    return *reinterpret_cast<unsigned*>(&h);
}
__device__ __forceinline__ void mma_f16(float* d,
                                        unsigned a0, unsigned a1, unsigned a2, unsigned a3,
                                        unsigned b0, unsigned b1) {
    asm volatile("mma.sync.aligned.m16n8k16.row.col.f32.f16.f16.f32 "
                 "{%0,%1,%2,%3}, {%4,%5,%6,%7}, {%8,%9}, {%0,%1,%2,%3};"
                 : "+f"(d[0]), "+f"(d[1]), "+f"(d[2]), "+f"(d[3])
                 : "r"(a0), "r"(a1), "r"(a2), "r"(a3), "r"(b0), "r"(b1));
}
__device__ __forceinline__ void bar_arrive(int idx) {
    asm volatile("red.release.gpu.global.add.u32 [%0], 1;" :: "l"(&g_bar[idx]) : "memory");
}
__device__ __forceinline__ void poll_n(int idx, unsigned n) {
    unsigned v;
    do {
        asm volatile("ld.acquire.gpu.global.u32 %0, [%1];" : "=r"(v) : "l"(&g_bar[idx]) : "memory");
    } while (v < n);
}
__device__ __forceinline__ float2 ldcg2(const float* p) {
    return __ldcg(reinterpret_cast<const float2*>(p));
}
__device__ __forceinline__ int pos_of(int p, int j1) {
    return (p & 3) * 4 + (p >> 2) * 2 + j1;
}

// ================= single persistent kernel =================
__global__ void __launch_bounds__(THREADS, 1)
cornn_persist(const float* __restrict__ x, const float* __restrict__ W,
              const float* __restrict__ bias,
              const float* __restrict__ Wout, const float* __restrict__ bout,
              float* __restrict__ out) {
    __shared__ float Part[KW * 16 * PS];   // 16 slabs x m16 x PS = 40,960 B

    const int tid  = threadIdx.x;
    const int cta  = blockIdx.x;
    const int mi   = cta >> 4;            // 0..7
    const int ni   = cta & 15;            // 0..15
    const int lane = tid & 31;
    const int warp = tid >> 5;            // 0..15
    const int kh   = warp & 7;            // k-slice of 128
    const int mh   = warp >> 3;           // row half (16 rows)
    const int rr   = lane >> 2;
    const int cc   = 2 * (lane & 3);

    // ================= phase 1: preX[t] = x_t @ W[0:128] + b (per-CTA patches) =================
    {
        unsigned xb0[8][4], xb1[8][4];
        const int n = ni * 32 + rr;
#pragma unroll
        for (int j = 0; j < 8; ++j) {
            const int k0 = j * 16 + cc;
#pragma unroll
            for (int nf = 0; nf < 4; ++nf) {
                const float* wp = W + (size_t)k0 * NHID + n + nf * 8;
                xb0[j][nf] = pack_h2(wp[0],        wp[NHID]);
                xb1[j][nf] = pack_h2(wp[8 * NHID], wp[9 * NHID]);
            }
        }
        float bc[4][2];
#pragma unroll
        for (int nf = 0; nf < 4; ++nf) {
            int col = ni * 32 + nf * 8 + cc;
            bc[nf][0] = bias[col];
            bc[nf][1] = bias[col + 1];
        }
        const int arow = mi * 32 + rr;
        for (int i = 0; i < TSTEPS / KW; ++i) {
            const int t = warp + KW * i;
            float acc0[4][4], acc1[4][4];
#pragma unroll
            for (int nf = 0; nf < 4; ++nf) {
                acc0[nf][0] = bc[nf][0]; acc0[nf][1] = bc[nf][1];
                acc0[nf][2] = bc[nf][0]; acc0[nf][3] = bc[nf][1];
                acc1[nf][0] = bc[nf][0]; acc1[nf][1] = bc[nf][1];
                acc1[nf][2] = bc[nf][0]; acc1[nf][3] = bc[nf][1];
            }
            const float* rx = x + ((size_t)t * BSZ + arow) * NIN + cc;
#pragma unroll
            for (int j = 0; j < 8; ++j) {
                float2 v0l = ldcg2(rx + j * 16),            v0h = ldcg2(rx + j * 16 + 8);
                float2 v1l = ldcg2(rx + 8 * NIN + j * 16),  v1h = ldcg2(rx + 8 * NIN + j * 16 + 8);
                float2 v2l = ldcg2(rx + 16 * NIN + j * 16), v2h = ldcg2(rx + 16 * NIN + j * 16 + 8);
                float2 v3l = ldcg2(rx + 24 * NIN + j * 16), v3h = ldcg2(rx + 24 * NIN + j * 16 + 8);
                unsigned a0l = pack_h2(v0l.x, v0l.y), a0h = pack_h2(v0h.x, v0h.y);
                unsigned a1l = pack_h2(v1l.x, v1l.y), a1h = pack_h2(v1h.x, v1h.y);
                unsigned a2l = pack_h2(v2l.x, v2l.y), a2h = pack_h2(v2h.x, v2h.y);
                unsigned a3l = pack_h2(v3l.x, v3l.y), a3h = pack_h2(v3h.x, v3h.y);
#pragma unroll
                for (int nf = 0; nf < 4; ++nf) {
                    mma_f16(acc0[nf], a0l, a1l, a0h, a1h, xb0[j][nf], xb1[j][nf]);
                    mma_f16(acc1[nf], a2l, a3l, a2h, a3h, xb0[j][nf], xb1[j][nf]);
                }
            }
            float* dst = g_preX + ((size_t)(cta * TSTEPS + t) * 32) * 32;
#pragma unroll
            for (int nf = 0; nf < 4; ++nf) {
                int co = nf * 8 + cc;
                __stcg((float2*)(dst + rr * 32 + co),        make_float2(acc0[nf][0], acc0[nf][1]));
                __stcg((float2*)(dst + (rr + 8) * 32 + co),  make_float2(acc0[nf][2], acc0[nf][3]));
                __stcg((float2*)(dst + (rr + 16) * 32 + co), make_float2(acc1[nf][0], acc1[nf][1]));
                __stcg((float2*)(dst + (rr + 24) * 32 + co), make_float2(acc1[nf][2], acc1[nf][3]));
            }
        }
    }

    // ================= producer store addresses (1 col-pair per thread) =================
    const int srow = tid >> 4;                 // 0..31
    const int scol = (tid & 15) * 2;           // 0,2,..,30
    const int grow = mi * 32 + srow;
    const int gcol = ni * 32 + scol;
    const int sl   = gcol >> 7;                // slice 0..3
    const int lc   = gcol & 127;
    const int jj   = lc >> 4;                  // k16-block within slice
    const int m0   = jj >> 1;                  // block-pair
    const int j1   = jj & 1;
    const int p0   = (lc & 15) >> 1;           // pair index 0..7
    const int a0i  = (((mi * 4 + sl) * 4 + m0) * 32 + srow) * 16 + pos_of(p0, j1);

    // zero initial state (buffer 0), per-warp arrive (t=0)
    __stcg(&g_Hz[0][a0i], 0u);
    __stcg(&g_Hy[0][a0i], 0u);
    __syncwarp();
    if (lane == 0) bar_arrive(BARIDX(0, mi));

    // ---- main-loop B fragments: W rows 128 + kh*128 .. +128 ----
    unsigned wb0[8][4], wb1[8][4];
    {
        const int n = ni * 32 + rr;
#pragma unroll
        for (int j = 0; j < 8; ++j) {
            const int k0 = 128 + kh * 128 + j * 16 + cc;
#pragma unroll
            for (int nf = 0; nf < 4; ++nf) {
                const float* wp = W + (size_t)k0 * NHID + n + nf * 8;
                wb0[j][nf] = pack_h2(wp[0],        wp[NHID]);
                wb1[j][nf] = pack_h2(wp[8 * NHID], wp[9 * NHID]);
            }
        }
    }

    // consumer A-fragment base: kh<4 -> hz slice kh, else hy slice kh-4; rows mh*16+
    const int hoff = (mi * 4 + (kh & 3)) * 2048 + mh * 256 + rr * 16 + (lane & 3) * 4;

    float hyr[2] = {0, 0}, hzr[2] = {0, 0};

    // preX prefetch one step ahead (this thread's float2 patch)
    const float* pxbase = g_preX + ((size_t)cta * TSTEPS * 32 + srow) * 32 + scol;
    float2 px = ldcg2(pxbase);

    // ================= recurrence =================
    for (int t = 0; t < TSTEPS; ++t) {
        const int rb = t & 1, wbuf = rb ^ 1;

        // prefetch next step's preX patch
        const int tn = (t + 1 < TSTEPS) ? t + 1 : t;
        float2 px_next = ldcg2(pxbase + (size_t)tn * 32 * 32);

        // per-warp poll: all 256 producer-warps of this mi group published step t
        if (lane == 0) poll_n(BARIDX(t, mi), ARRIVALS);
        __syncwarp();

        const unsigned* hp = ((kh < 4) ? g_Hz[rb] : g_Hy[rb]) + hoff;

        float acc[4][4];
#pragma unroll
        for (int nf = 0; nf < 4; ++nf)
#pragma unroll
            for (int c = 0; c < 4; ++c) acc[nf][c] = 0.f;

#pragma unroll
        for (int m = 0; m < 4; ++m) {
            const unsigned* q = hp + m * 512;     // block-pair m; rows +8 -> +128 u32
            uint4 u0 = __ldcg((const uint4*)(q));            // rows mh*16 + 0..7
            uint4 u1 = __ldcg((const uint4*)(q + 128));      // rows mh*16 + 8..15
            // even block (j = 2m): .x (pair c), .z (pair c+4)
#pragma unroll
            for (int nf = 0; nf < 4; ++nf)
                mma_f16(acc[nf], u0.x, u1.x, u0.z, u1.z, wb0[2*m][nf], wb1[2*m][nf]);
            // odd block (j = 2m+1): .y, .w
#pragma unroll
            for (int nf = 0; nf < 4; ++nf)
                mma_f16(acc[nf], u0.y, u1.y, u0.w, u1.w, wb0[2*m+1][nf], wb1[2*m+1][nf]);
        }

        // write this warp's m16 x n32 partial (slab = warp)
        {
            float* P = Part + warp * (16 * PS);
#pragma unroll
            for (int nf = 0; nf < 4; ++nf) {
                int co = nf * 8 + cc;
                *(float2*)(P + rr * PS + co)       = make_float2(acc[nf][0], acc[nf][1]);
                *(float2*)(P + (rr + 8) * PS + co) = make_float2(acc[nf][2], acc[nf][3]);
            }
        }
        __syncthreads();   // single CTA-wide barrier: partials visible

        // reduce 8 k-slice partials (own m-half) + preX, tanh, update, publish
        {
            const float* Pb = Part + ((srow >> 4) * 8) * (16 * PS) + (srow & 15) * PS + scol;
            float s0 = px.x, s1 = px.y;
#pragma unroll
            for (int p = 0; p < 8; ++p) {
                float2 v = *(const float2*)(Pb + p * (16 * PS));
                s0 += v.x; s1 += v.y;
            }
            float pre0 = fast_tanh(s0);
            float pre1 = fast_tanh(s1);
            hzr[0] += DTc * (pre0 - GAMc * hyr[0] - EPSc * hzr[0]);  hyr[0] += DTc * hzr[0];
            hzr[1] += DTc * (pre1 - GAMc * hyr[1] - EPSc * hzr[1]);  hyr[1] += DTc * hzr[1];

            __stcg(&g_Hz[wbuf][a0i], pack_h2(hzr[0], hzr[1]));
            __stcg(&g_Hy[wbuf][a0i], pack_h2(hyr[0], hyr[1]));
            if (t == TSTEPS - 1) {
                __stcg((float2*)&g_hyf[(size_t)grow * NHID + gcol],
                       make_float2(hyr[0], hyr[1]));
            }
        }
        __syncwarp();
        if (lane == 0) bar_arrive(BARIDX(t + 1, mi));   // this warp's rows published
        px = px_next;
    }

    // ---- final wait: all 256 producer-warps of rows mi done ----
    if (tid == 0) poll_n(BARIDX(TSTEPS, mi), ARRIVALS);
    __syncthreads();

    // ---- fused output GEMM: out = hy_final @ Wout + bout ----
    if (warp < 2) {
        int row = cta * 2 + warp;
        const float* h = g_hyf + (size_t)row * NHID;
        float acc[NOUT];
#pragma unroll
        for (int o = 0; o < NOUT; ++o) acc[o] = 0.f;
        for (int k = lane; k < NHID; k += 32) {
            float hv = __ldcg(h + k);
#pragma unroll
            for (int o = 0; o < NOUT; ++o) acc[o] += hv * Wout[k * NOUT + o];
        }
#pragma unroll
        for (int o = 0; o < NOUT; ++o) {
#pragma unroll
            for (int s = 16; s > 0; s >>= 1)
                acc[o] += __shfl_xor_sync(0xffffffffu, acc[o], s);
        }
        if (lane == 0) {
#pragma unroll
            for (int o = 0; o < NOUT; ++o) out[row * NOUT + o] = acc[o] + bout[o];
        }
    }

    // ---- safe self-reset: last CTA of mi group (all pollers of mi already done) ----
    __shared__ unsigned s_last;
    if (tid == 0) {
        unsigned old = atomicAdd(&g_fin[mi], 1u);
        s_last = (old == 15u) ? 1u : 0u;
    }
    __syncthreads();
    if (s_last) {
        for (int tt = tid; tt <= TSTEPS; tt += THREADS)
            g_bar[BARIDX(tt, mi)] = 0u;
        __syncthreads();
        if (tid == 0) {
            __threadfence();
            g_fin[mi] = 0u;
        }
    }
}

// ---------------- launch ----------------
extern "C" void kernel_launch(void* const* d_in, const int* in_sizes, int n_in,
                              void* d_out, int out_size) {
    (void)in_sizes; (void)n_in; (void)out_size;
    const float* x    = (const float*)d_in[0];
    const float* W    = (const float*)d_in[1];
    const float* b    = (const float*)d_in[2];
    const float* Wout = (const float*)d_in[3];
    const float* bout = (const float*)d_in[4];
    float* out = (float*)d_out;

    cornn_persist<<<NCTA, THREADS>>>(x, W, b, Wout, bout, out);
}